// round 1
// baseline (speedup 1.0000x reference)
#include <cuda_runtime.h>
#include <math.h>

#define NN 50000
#define EE 800000
#define NDIM 32
#define EDIM 16
#define HID 96
#define NHEAD 4
#define CPH 24

// ---------------- scratch (device globals; no runtime allocation) ----------
__device__ float  g_h[NN * HID];
__device__ float  g_xl[NN * HID];
__device__ float  g_xr[NN * HID];
__device__ float4 g_alpha[EE];
__device__ int    g_rowptr[NN + 1];
__device__ int    g_cursor[NN];
__device__ int    g_eid[EE];

// ---------------- CSR build ------------------------------------------------
__global__ void k_zero() {
    int i = blockIdx.x * blockDim.x + threadIdx.x;
    if (i <= NN) g_rowptr[i] = 0;
}

__global__ void k_count(const int* __restrict__ dst) {
    int e = blockIdx.x * blockDim.x + threadIdx.x;
    if (e < EE) atomicAdd(&g_rowptr[dst[e] + 1], 1);
}

// single-block inclusive scan over rowptr[0..NN] (rowptr[i+1] holds count[i])
__global__ void k_scan() {
    __shared__ int sh[1024];
    __shared__ int s_carry;
    int tid = threadIdx.x;
    if (tid == 0) s_carry = 0;
    __syncthreads();
    for (int base = 0; base < NN + 1; base += 1024) {
        int i = base + tid;
        int v = (i < NN + 1) ? g_rowptr[i] : 0;
        sh[tid] = v;
        __syncthreads();
        for (int off = 1; off < 1024; off <<= 1) {
            int t = (tid >= off) ? sh[tid - off] : 0;
            __syncthreads();
            sh[tid] += t;
            __syncthreads();
        }
        int out = sh[tid] + s_carry;
        if (i < NN + 1) g_rowptr[i] = out;
        if (i < NN)     g_cursor[i] = out;
        __syncthreads();
        if (tid == 1023) s_carry += sh[1023];
        __syncthreads();
    }
}

__global__ void k_fill(const int* __restrict__ dst) {
    int e = blockIdx.x * blockDim.x + threadIdx.x;
    if (e < EE) {
        int p = atomicAdd(&g_cursor[dst[e]], 1);
        g_eid[p] = e;
    }
}

// ---------------- dense node linear: out[N,96] = in[N,KIN] @ W[KIN,96] + b -
// 96 threads/block (thread = output column, weights in registers),
// 4 nodes per block via smem broadcast.
template <int KIN>
__global__ void k_lin(const float* __restrict__ in, const float* __restrict__ W,
                      const float* __restrict__ bias, float* __restrict__ out) {
    __shared__ float h_sh[4 * KIN];
    int tid = threadIdx.x;  // 0..95
    float wreg[KIN];
#pragma unroll
    for (int k = 0; k < KIN; k++) wreg[k] = W[k * HID + tid];
    float bv = bias[tid];
    int n0 = blockIdx.x * 4;
    for (int idx = tid; idx < 4 * KIN; idx += 96) {
        int nn = n0 + idx / KIN;
        h_sh[idx] = (nn < NN) ? in[n0 * KIN + idx] : 0.f;
    }
    __syncthreads();
    float a0 = bv, a1 = bv, a2 = bv, a3 = bv;
#pragma unroll
    for (int k = 0; k < KIN; k++) {
        float w = wreg[k];
        a0 = fmaf(h_sh[0 * KIN + k], w, a0);
        a1 = fmaf(h_sh[1 * KIN + k], w, a1);
        a2 = fmaf(h_sh[2 * KIN + k], w, a2);
        a3 = fmaf(h_sh[3 * KIN + k], w, a3);
    }
    if (n0 + 0 < NN) out[(n0 + 0) * HID + tid] = a0;
    if (n0 + 1 < NN) out[(n0 + 1) * HID + tid] = a1;
    if (n0 + 2 < NN) out[(n0 + 2) * HID + tid] = a2;
    if (n0 + 3 < NN) out[(n0 + 3) * HID + tid] = a3;
}

// ---------------- edge kernel: raw attention logits per edge/head ----------
// warp per edge: e = edge_attr @ We (We in smem, edge_attr via shuffle),
// m = leaky_relu(xl[src]+xr[dst]+e), alpha[h] = sum_c m*att
__global__ void k_edge(const int* __restrict__ src_arr, const int* __restrict__ dst_arr,
                       const float* __restrict__ eattr, const float* __restrict__ We,
                       const float* __restrict__ att) {
    __shared__ float We_sh[EDIM * HID];
    __shared__ float att_sh[HID];
    int tid = threadIdx.x;
    for (int i = tid; i < EDIM * HID; i += 256) We_sh[i] = We[i];
    if (tid < HID) att_sh[tid] = att[tid];
    __syncthreads();

    int lane = tid & 31;
    int e = blockIdx.x * 8 + (tid >> 5);
    if (e >= EE) return;

    float ea = (lane < EDIM) ? eattr[e * EDIM + lane] : 0.f;
    int s = src_arr[e], d = dst_arr[e];
    int c0 = lane, c1 = lane + 32, c2 = lane + 64;

    float e0 = 0.f, e1 = 0.f, e2 = 0.f;
#pragma unroll
    for (int k = 0; k < EDIM; k++) {
        float a = __shfl_sync(0xffffffffu, ea, k);
        e0 = fmaf(a, We_sh[k * HID + c0], e0);
        e1 = fmaf(a, We_sh[k * HID + c1], e1);
        e2 = fmaf(a, We_sh[k * HID + c2], e2);
    }
    const float* xlp = g_xl + s * HID;
    const float* xrp = g_xr + d * HID;
    float m0 = xlp[c0] + xrp[c0] + e0;
    float m1 = xlp[c1] + xrp[c1] + e1;
    float m2 = xlp[c2] + xrp[c2] + e2;
    m0 = fmaxf(m0, 0.2f * m0);
    m1 = fmaxf(m1, 0.2f * m1);
    m2 = fmaxf(m2, 0.2f * m2);
    float v0 = m0 * att_sh[c0];
    float v1 = m1 * att_sh[c1];
    float v2 = m2 * att_sh[c2];

    // head mapping: c/24. c0 in [0,32): h0|h1 ; c1 in [32,64): h1|h2 ; c2 in [64,96): h2|h3
    float p0 = 0.f, p1 = 0.f, p2 = 0.f, p3 = 0.f;
    if (lane < 24) p0 += v0; else p1 += v0;
    if (lane < 16) p1 += v1; else p2 += v1;
    if (lane < 8)  p2 += v2; else p3 += v2;
#pragma unroll
    for (int off = 16; off; off >>= 1) {
        p0 += __shfl_xor_sync(0xffffffffu, p0, off);
        p1 += __shfl_xor_sync(0xffffffffu, p1, off);
        p2 += __shfl_xor_sync(0xffffffffu, p2, off);
        p3 += __shfl_xor_sync(0xffffffffu, p3, off);
    }
    if (lane == 0) g_alpha[e] = make_float4(p0, p1, p2, p3);
}

// ---------------- aggregate + softmax + residual + LayerNorm, warp/node ----
__global__ void k_aggr(const int* __restrict__ src_arr, const float* __restrict__ cb,
                       const float* __restrict__ lng, const float* __restrict__ lnb) {
    int lane = threadIdx.x & 31;
    int n = blockIdx.x * 8 + (threadIdx.x >> 5);
    if (n >= NN) return;

    int r0 = g_rowptr[n], r1 = g_rowptr[n + 1];
    int c0 = lane, c1 = lane + 32, c2 = lane + 64;
    float acc0 = 0.f, acc1 = 0.f, acc2 = 0.f;

    if (r1 > r0) {
        // pass 1: per-head max
        float mx0 = -3e38f, mx1 = -3e38f, mx2 = -3e38f, mx3 = -3e38f;
        for (int i = r0 + lane; i < r1; i += 32) {
            float4 a = g_alpha[g_eid[i]];
            mx0 = fmaxf(mx0, a.x); mx1 = fmaxf(mx1, a.y);
            mx2 = fmaxf(mx2, a.z); mx3 = fmaxf(mx3, a.w);
        }
#pragma unroll
        for (int off = 16; off; off >>= 1) {
            mx0 = fmaxf(mx0, __shfl_xor_sync(0xffffffffu, mx0, off));
            mx1 = fmaxf(mx1, __shfl_xor_sync(0xffffffffu, mx1, off));
            mx2 = fmaxf(mx2, __shfl_xor_sync(0xffffffffu, mx2, off));
            mx3 = fmaxf(mx3, __shfl_xor_sync(0xffffffffu, mx3, off));
        }
        // pass 2: exp + denom; overwrite alpha with exp values
        float s0 = 0.f, s1 = 0.f, s2 = 0.f, s3 = 0.f;
        for (int i = r0 + lane; i < r1; i += 32) {
            int eid = g_eid[i];
            float4 a = g_alpha[eid];
            a.x = __expf(a.x - mx0); a.y = __expf(a.y - mx1);
            a.z = __expf(a.z - mx2); a.w = __expf(a.w - mx3);
            g_alpha[eid] = a;
            s0 += a.x; s1 += a.y; s2 += a.z; s3 += a.w;
        }
#pragma unroll
        for (int off = 16; off; off >>= 1) {
            s0 += __shfl_xor_sync(0xffffffffu, s0, off);
            s1 += __shfl_xor_sync(0xffffffffu, s1, off);
            s2 += __shfl_xor_sync(0xffffffffu, s2, off);
            s3 += __shfl_xor_sync(0xffffffffu, s3, off);
        }
        float i0 = 1.f / (s0 + 1e-16f), i1 = 1.f / (s1 + 1e-16f);
        float i2 = 1.f / (s2 + 1e-16f), i3 = 1.f / (s3 + 1e-16f);
        float invA = (lane < 24) ? i0 : i1;
        float invB = (lane < 16) ? i1 : i2;
        float invC = (lane < 8)  ? i2 : i3;
        __syncwarp();  // make lane-written exp(alpha) visible warp-wide
        // pass 3: weighted gather of xl[src]
        for (int i = r0; i < r1; i++) {
            int eid = g_eid[i];
            float4 a = g_alpha[eid];
            int s = src_arr[eid];
            const float* xlp = g_xl + s * HID;
            float wA = ((lane < 24) ? a.x : a.y) * invA;
            float wB = ((lane < 16) ? a.y : a.z) * invB;
            float wC = ((lane < 8)  ? a.z : a.w) * invC;
            acc0 = fmaf(wA, xlp[c0], acc0);
            acc1 = fmaf(wB, xlp[c1], acc1);
            acc2 = fmaf(wC, xlp[c2], acc2);
        }
    }
    // residual + conv bias + LayerNorm (warp-wide over 96 channels)
    float h0 = g_h[n * HID + c0] + acc0 + cb[c0];
    float h1 = g_h[n * HID + c1] + acc1 + cb[c1];
    float h2 = g_h[n * HID + c2] + acc2 + cb[c2];
    float sm = h0 + h1 + h2;
#pragma unroll
    for (int off = 16; off; off >>= 1) sm += __shfl_xor_sync(0xffffffffu, sm, off);
    float mu = sm * (1.f / 96.f);
    float d0 = h0 - mu, d1 = h1 - mu, d2 = h2 - mu;
    float vv = d0 * d0 + d1 * d1 + d2 * d2;
#pragma unroll
    for (int off = 16; off; off >>= 1) vv += __shfl_xor_sync(0xffffffffu, vv, off);
    float rs = rsqrtf(vv * (1.f / 96.f) + 1e-5f);
    g_h[n * HID + c0] = d0 * rs * lng[c0] + lnb[c0];
    g_h[n * HID + c1] = d1 * rs * lng[c1] + lnb[c1];
    g_h[n * HID + c2] = d2 * rs * lng[c2] + lnb[c2];
}

// ---------------- MLP head: gelu(h@w1+b1)@w2+b2 ----------------------------
__global__ void __launch_bounds__(64) k_head(const float* __restrict__ w1,
                                             const float* __restrict__ b1,
                                             const float* __restrict__ w2,
                                             const float* __restrict__ b2,
                                             float* __restrict__ out) {
    __shared__ float w1s[HID * 48];
    __shared__ float b1s[48];
    __shared__ float w2s[48];
    __shared__ float hs[64 * 97];  // pad to 97 to avoid bank conflicts
    int tid = threadIdx.x;
    for (int i = tid; i < HID * 48; i += 64) w1s[i] = w1[i];
    if (tid < 48) { b1s[tid] = b1[tid]; w2s[tid] = w2[tid]; }
    int n0 = blockIdx.x * 64;
    for (int idx = tid; idx < 64 * HID; idx += 64) {
        int nn = idx / HID, k = idx % HID;
        hs[nn * 97 + k] = (n0 + nn < NN) ? g_h[n0 * HID + idx] : 0.f;
    }
    __syncthreads();
    int node = n0 + tid;
    if (node >= NN) return;
    float y = 0.f;
#pragma unroll 4
    for (int j = 0; j < 48; j++) {
        float a = b1s[j];
#pragma unroll
        for (int k = 0; k < HID; k++) a = fmaf(hs[tid * 97 + k], w1s[k * 48 + j], a);
        float ge = 0.5f * a * (1.f + erff(a * 0.70710678118654752f));  // exact gelu
        y = fmaf(ge, w2s[j], y);
    }
    out[node] = y + b2[0];
}

// ---------------- launch ---------------------------------------------------
extern "C" void kernel_launch(void* const* d_in, const int* in_sizes, int n_in,
                              void* d_out, int out_size) {
    const float* x      = (const float*)d_in[0];
    const int*   ei     = (const int*)d_in[1];
    const float* eattr  = (const float*)d_in[2];
    const float* proj_w = (const float*)d_in[3];
    const float* proj_b = (const float*)d_in[4];
    const float* ll_w   = (const float*)d_in[5];
    const float* ll_b   = (const float*)d_in[6];
    const float* lr_w   = (const float*)d_in[7];
    const float* lr_b   = (const float*)d_in[8];
    const float* le_w   = (const float*)d_in[9];
    const float* att    = (const float*)d_in[10];
    const float* cb     = (const float*)d_in[11];
    const float* lng    = (const float*)d_in[12];
    const float* lnb    = (const float*)d_in[13];
    const float* hw1    = (const float*)d_in[14];
    const float* hb1    = (const float*)d_in[15];
    const float* hw2    = (const float*)d_in[16];
    const float* hb2    = (const float*)d_in[17];
    float* out = (float*)d_out;

    const int* src = ei;
    const int* dst = ei + EE;

    float *ph, *pxl, *pxr;
    cudaGetSymbolAddress((void**)&ph,  g_h);
    cudaGetSymbolAddress((void**)&pxl, g_xl);
    cudaGetSymbolAddress((void**)&pxr, g_xr);

    // CSR build (once per call; reused by all 3 layers)
    k_zero<<<(NN + 256) / 256, 256>>>();
    k_count<<<(EE + 255) / 256, 256>>>(dst);
    k_scan<<<1, 1024>>>();
    k_fill<<<(EE + 255) / 256, 256>>>(dst);

    // input projection
    k_lin<NDIM><<<(NN + 3) / 4, 96>>>(x, proj_w, proj_b, ph);

    for (int l = 0; l < 3; l++) {
        k_lin<HID><<<(NN + 3) / 4, 96>>>(ph, ll_w + l * HID * HID, ll_b + l * HID, pxl);
        k_lin<HID><<<(NN + 3) / 4, 96>>>(ph, lr_w + l * HID * HID, lr_b + l * HID, pxr);
        k_edge<<<(EE + 7) / 8, 256>>>(src, dst, eattr, le_w + l * EDIM * HID, att + l * HID);
        k_aggr<<<(NN + 7) / 8, 256>>>(src, cb + l * HID, lng + l * HID, lnb + l * HID);
    }

    k_head<<<(NN + 63) / 64, 64>>>(hw1, hb1, hw2, hb2, out);
}

// round 2
// speedup vs baseline: 1.1451x; 1.1451x over previous
#include <cuda_runtime.h>
#include <math.h>

#define NN 50000
#define EE 800000
#define NDIM 32
#define EDIM 16
#define HID 96
#define NHEAD 4
#define CPH 24

// ---------------- scratch (device globals; no runtime allocation) ----------
__device__ float  g_h[NN * HID];
__device__ float  g_xl[NN * HID];
__device__ float  g_xr[NN * HID];
__device__ float4 g_alpha[EE];
__device__ int    g_rowptr[NN + 1];
__device__ int    g_cursor[NN];
__device__ int    g_eid[EE];

// ---------------- CSR build ------------------------------------------------
__global__ void k_zero() {
    int i = blockIdx.x * blockDim.x + threadIdx.x;
    if (i <= NN) g_rowptr[i] = 0;
}

__global__ void k_count(const int* __restrict__ dst) {
    int e = blockIdx.x * blockDim.x + threadIdx.x;
    if (e < EE) atomicAdd(&g_rowptr[dst[e] + 1], 1);
}

// single-block inclusive scan over rowptr[0..NN]
__global__ void k_scan() {
    __shared__ int sh[1024];
    __shared__ int s_carry;
    int tid = threadIdx.x;
    if (tid == 0) s_carry = 0;
    __syncthreads();
    for (int base = 0; base < NN + 1; base += 1024) {
        int i = base + tid;
        int v = (i < NN + 1) ? g_rowptr[i] : 0;
        sh[tid] = v;
        __syncthreads();
        for (int off = 1; off < 1024; off <<= 1) {
            int t = (tid >= off) ? sh[tid - off] : 0;
            __syncthreads();
            sh[tid] += t;
            __syncthreads();
        }
        int out = sh[tid] + s_carry;
        if (i < NN + 1) g_rowptr[i] = out;
        if (i < NN)     g_cursor[i] = out;
        __syncthreads();
        if (tid == 1023) s_carry += sh[1023];
        __syncthreads();
    }
}

__global__ void k_fill(const int* __restrict__ dst) {
    int e = blockIdx.x * blockDim.x + threadIdx.x;
    if (e < EE) {
        int p = atomicAdd(&g_cursor[dst[e]], 1);
        g_eid[p] = e;
    }
}

// ---------------- proj: out[N,96] = in[N,32] @ W + b (persistent) ----------
__global__ void __launch_bounds__(96) k_proj(const float* __restrict__ in,
                                             const float* __restrict__ W,
                                             const float* __restrict__ bias,
                                             float* __restrict__ out) {
    __shared__ float h_sh[16 * NDIM];
    int tid = threadIdx.x;  // 0..95 = output column
    float wreg[NDIM];
#pragma unroll
    for (int k = 0; k < NDIM; k++) wreg[k] = W[k * HID + tid];
    float bv = bias[tid];
    for (int n0 = blockIdx.x * 16; n0 < NN; n0 += gridDim.x * 16) {
        __syncthreads();
        for (int idx = tid; idx < 16 * NDIM; idx += 96) {
            int nn = n0 + idx / NDIM;
            h_sh[idx] = (nn < NN) ? in[n0 * NDIM + idx] : 0.f;
        }
        __syncthreads();
        float acc[16];
#pragma unroll
        for (int j = 0; j < 16; j++) acc[j] = bv;
#pragma unroll
        for (int k = 0; k < NDIM; k += 4) {
#pragma unroll
            for (int j = 0; j < 16; j++) {
                float4 hv = *(const float4*)&h_sh[j * NDIM + k];
                acc[j] = fmaf(hv.x, wreg[k + 0], acc[j]);
                acc[j] = fmaf(hv.y, wreg[k + 1], acc[j]);
                acc[j] = fmaf(hv.z, wreg[k + 2], acc[j]);
                acc[j] = fmaf(hv.w, wreg[k + 3], acc[j]);
            }
        }
#pragma unroll
        for (int j = 0; j < 16; j++)
            if (n0 + j < NN) out[(n0 + j) * HID + tid] = acc[j];
    }
}

// ---------------- fused lin_l + lin_r (persistent, weights in registers) ---
// 192 threads: tid<96 computes xl column tid, tid>=96 computes xr column.
__global__ void __launch_bounds__(192) k_lin2(const float* __restrict__ in,
                                              const float* __restrict__ Wl,
                                              const float* __restrict__ bl,
                                              const float* __restrict__ Wr,
                                              const float* __restrict__ br,
                                              float* __restrict__ outl,
                                              float* __restrict__ outr) {
    __shared__ float h_sh[16 * HID];  // 6 KB input tile, 16 nodes
    int tid = threadIdx.x;
    int col = tid % 96;
    bool isR = tid >= 96;
    const float* W = isR ? Wr : Wl;
    float wreg[HID];
#pragma unroll
    for (int k = 0; k < HID; k++) wreg[k] = W[k * HID + col];
    float bv = isR ? br[col] : bl[col];
    float* out = isR ? outr : outl;

    for (int n0 = blockIdx.x * 16; n0 < NN; n0 += gridDim.x * 16) {
        __syncthreads();
        for (int idx = tid; idx < 16 * HID; idx += 192) {
            int nn = n0 + idx / HID;
            h_sh[idx] = (nn < NN) ? in[n0 * HID + idx] : 0.f;
        }
        __syncthreads();
        float acc[16];
#pragma unroll
        for (int j = 0; j < 16; j++) acc[j] = bv;
#pragma unroll
        for (int k = 0; k < HID; k += 4) {
#pragma unroll
            for (int j = 0; j < 16; j++) {
                float4 hv = *(const float4*)&h_sh[j * HID + k];
                acc[j] = fmaf(hv.x, wreg[k + 0], acc[j]);
                acc[j] = fmaf(hv.y, wreg[k + 1], acc[j]);
                acc[j] = fmaf(hv.z, wreg[k + 2], acc[j]);
                acc[j] = fmaf(hv.w, wreg[k + 3], acc[j]);
            }
        }
#pragma unroll
        for (int j = 0; j < 16; j++)
            if (n0 + j < NN) out[(n0 + j) * HID + col] = acc[j];
    }
}

// ---------------- edge kernel (persistent): raw attention logits -----------
__global__ void __launch_bounds__(256) k_edge(const int* __restrict__ src_arr,
                                              const int* __restrict__ dst_arr,
                                              const float* __restrict__ eattr,
                                              const float* __restrict__ We,
                                              const float* __restrict__ att) {
    __shared__ float We_sh[EDIM * HID];
    __shared__ float att_sh[HID];
    int tid = threadIdx.x;
    for (int i = tid; i < EDIM * HID; i += 256) We_sh[i] = We[i];
    if (tid < HID) att_sh[tid] = att[tid];
    __syncthreads();

    int lane = tid & 31;
    int w = tid >> 5;

    for (int e = blockIdx.x * 8 + w; e < EE; e += gridDim.x * 8) {
        float ea = (lane < EDIM) ? eattr[e * EDIM + lane] : 0.f;
        int s = src_arr[e], d = dst_arr[e];
        int c0 = lane, c1 = lane + 32, c2 = lane + 64;

        float e0 = 0.f, e1 = 0.f, e2 = 0.f;
#pragma unroll
        for (int k = 0; k < EDIM; k++) {
            float a = __shfl_sync(0xffffffffu, ea, k);
            e0 = fmaf(a, We_sh[k * HID + c0], e0);
            e1 = fmaf(a, We_sh[k * HID + c1], e1);
            e2 = fmaf(a, We_sh[k * HID + c2], e2);
        }
        const float* xlp = g_xl + s * HID;
        const float* xrp = g_xr + d * HID;
        float m0 = xlp[c0] + xrp[c0] + e0;
        float m1 = xlp[c1] + xrp[c1] + e1;
        float m2 = xlp[c2] + xrp[c2] + e2;
        m0 = fmaxf(m0, 0.2f * m0);
        m1 = fmaxf(m1, 0.2f * m1);
        m2 = fmaxf(m2, 0.2f * m2);
        float v0 = m0 * att_sh[c0];
        float v1 = m1 * att_sh[c1];
        float v2 = m2 * att_sh[c2];

        float p0 = 0.f, p1 = 0.f, p2 = 0.f, p3 = 0.f;
        if (lane < 24) p0 += v0; else p1 += v0;
        if (lane < 16) p1 += v1; else p2 += v1;
        if (lane < 8)  p2 += v2; else p3 += v2;
#pragma unroll
        for (int off = 16; off; off >>= 1) {
            p0 += __shfl_xor_sync(0xffffffffu, p0, off);
            p1 += __shfl_xor_sync(0xffffffffu, p1, off);
            p2 += __shfl_xor_sync(0xffffffffu, p2, off);
            p3 += __shfl_xor_sync(0xffffffffu, p3, off);
        }
        if (lane == 0) g_alpha[e] = make_float4(p0, p1, p2, p3);
    }
}

// ---------------- aggregate + softmax + residual + LayerNorm, warp/node ----
__global__ void __launch_bounds__(256) k_aggr(const int* __restrict__ src_arr,
                                              const float* __restrict__ cb,
                                              const float* __restrict__ lng,
                                              const float* __restrict__ lnb) {
    int lane = threadIdx.x & 31;
    int n = blockIdx.x * 8 + (threadIdx.x >> 5);
    if (n >= NN) return;

    int r0 = g_rowptr[n], r1 = g_rowptr[n + 1];
    int c0 = lane, c1 = lane + 32, c2 = lane + 64;
    float acc0 = 0.f, acc1 = 0.f, acc2 = 0.f;

    if (r1 > r0) {
        float mx0 = -3e38f, mx1 = -3e38f, mx2 = -3e38f, mx3 = -3e38f;
        for (int i = r0 + lane; i < r1; i += 32) {
            float4 a = g_alpha[g_eid[i]];
            mx0 = fmaxf(mx0, a.x); mx1 = fmaxf(mx1, a.y);
            mx2 = fmaxf(mx2, a.z); mx3 = fmaxf(mx3, a.w);
        }
#pragma unroll
        for (int off = 16; off; off >>= 1) {
            mx0 = fmaxf(mx0, __shfl_xor_sync(0xffffffffu, mx0, off));
            mx1 = fmaxf(mx1, __shfl_xor_sync(0xffffffffu, mx1, off));
            mx2 = fmaxf(mx2, __shfl_xor_sync(0xffffffffu, mx2, off));
            mx3 = fmaxf(mx3, __shfl_xor_sync(0xffffffffu, mx3, off));
        }
        float s0 = 0.f, s1 = 0.f, s2 = 0.f, s3 = 0.f;
        for (int i = r0 + lane; i < r1; i += 32) {
            int eid = g_eid[i];
            float4 a = g_alpha[eid];
            a.x = __expf(a.x - mx0); a.y = __expf(a.y - mx1);
            a.z = __expf(a.z - mx2); a.w = __expf(a.w - mx3);
            g_alpha[eid] = a;
            s0 += a.x; s1 += a.y; s2 += a.z; s3 += a.w;
        }
#pragma unroll
        for (int off = 16; off; off >>= 1) {
            s0 += __shfl_xor_sync(0xffffffffu, s0, off);
            s1 += __shfl_xor_sync(0xffffffffu, s1, off);
            s2 += __shfl_xor_sync(0xffffffffu, s2, off);
            s3 += __shfl_xor_sync(0xffffffffu, s3, off);
        }
        float i0 = 1.f / (s0 + 1e-16f), i1 = 1.f / (s1 + 1e-16f);
        float i2 = 1.f / (s2 + 1e-16f), i3 = 1.f / (s3 + 1e-16f);
        float invA = (lane < 24) ? i0 : i1;
        float invB = (lane < 16) ? i1 : i2;
        float invC = (lane < 8)  ? i2 : i3;
        __syncwarp();
        for (int i = r0; i < r1; i++) {
            int eid = g_eid[i];
            float4 a = g_alpha[eid];
            int s = src_arr[eid];
            const float* xlp = g_xl + s * HID;
            float wA = ((lane < 24) ? a.x : a.y) * invA;
            float wB = ((lane < 16) ? a.y : a.z) * invB;
            float wC = ((lane < 8)  ? a.z : a.w) * invC;
            acc0 = fmaf(wA, xlp[c0], acc0);
            acc1 = fmaf(wB, xlp[c1], acc1);
            acc2 = fmaf(wC, xlp[c2], acc2);
        }
    }
    float h0 = g_h[n * HID + c0] + acc0 + cb[c0];
    float h1 = g_h[n * HID + c1] + acc1 + cb[c1];
    float h2 = g_h[n * HID + c2] + acc2 + cb[c2];
    float sm = h0 + h1 + h2;
#pragma unroll
    for (int off = 16; off; off >>= 1) sm += __shfl_xor_sync(0xffffffffu, sm, off);
    float mu = sm * (1.f / 96.f);
    float d0 = h0 - mu, d1 = h1 - mu, d2 = h2 - mu;
    float vv = d0 * d0 + d1 * d1 + d2 * d2;
#pragma unroll
    for (int off = 16; off; off >>= 1) vv += __shfl_xor_sync(0xffffffffu, vv, off);
    float rs = rsqrtf(vv * (1.f / 96.f) + 1e-5f);
    g_h[n * HID + c0] = d0 * rs * lng[c0] + lnb[c0];
    g_h[n * HID + c1] = d1 * rs * lng[c1] + lnb[c1];
    g_h[n * HID + c2] = d2 * rs * lng[c2] + lnb[c2];
}

// ---------------- MLP head: gelu(h@w1+b1)@w2+b2 ----------------------------
// Thread = node; node's 96 h values hoisted to registers; w1 broadcast via
// float4 smem reads (1 LDS.128 per 4 FMA).
__global__ void __launch_bounds__(128) k_head(const float* __restrict__ w1,
                                              const float* __restrict__ b1,
                                              const float* __restrict__ w2,
                                              const float* __restrict__ b2,
                                              float* __restrict__ out) {
    __shared__ float w1s[HID * 48];  // 18 KB
    __shared__ float b1s[48];
    __shared__ float w2s[48];
    int tid = threadIdx.x;
    for (int i = tid; i < HID * 48; i += 128) w1s[i] = w1[i];
    if (tid < 48) { b1s[tid] = b1[tid]; w2s[tid] = w2[tid]; }
    __syncthreads();
    int node = blockIdx.x * 128 + tid;
    if (node >= NN) return;

    float hreg[HID];
#pragma unroll
    for (int k = 0; k < HID; k += 4) {
        float4 v = *(const float4*)&g_h[node * HID + k];
        hreg[k] = v.x; hreg[k + 1] = v.y; hreg[k + 2] = v.z; hreg[k + 3] = v.w;
    }
    float y = 0.f;
#pragma unroll 2
    for (int j = 0; j < 48; j += 4) {
        float a0 = b1s[j], a1 = b1s[j + 1], a2 = b1s[j + 2], a3 = b1s[j + 3];
#pragma unroll
        for (int k = 0; k < HID; k++) {
            float4 wv = *(const float4*)&w1s[k * 48 + j];
            a0 = fmaf(hreg[k], wv.x, a0);
            a1 = fmaf(hreg[k], wv.y, a1);
            a2 = fmaf(hreg[k], wv.z, a2);
            a3 = fmaf(hreg[k], wv.w, a3);
        }
        float g0 = 0.5f * a0 * (1.f + erff(a0 * 0.70710678118654752f));
        float g1 = 0.5f * a1 * (1.f + erff(a1 * 0.70710678118654752f));
        float g2 = 0.5f * a2 * (1.f + erff(a2 * 0.70710678118654752f));
        float g3 = 0.5f * a3 * (1.f + erff(a3 * 0.70710678118654752f));
        y = fmaf(g0, w2s[j], y);
        y = fmaf(g1, w2s[j + 1], y);
        y = fmaf(g2, w2s[j + 2], y);
        y = fmaf(g3, w2s[j + 3], y);
    }
    out[node] = y + b2[0];
}

// ---------------- launch ---------------------------------------------------
extern "C" void kernel_launch(void* const* d_in, const int* in_sizes, int n_in,
                              void* d_out, int out_size) {
    const float* x      = (const float*)d_in[0];
    const int*   ei     = (const int*)d_in[1];
    const float* eattr  = (const float*)d_in[2];
    const float* proj_w = (const float*)d_in[3];
    const float* proj_b = (const float*)d_in[4];
    const float* ll_w   = (const float*)d_in[5];
    const float* ll_b   = (const float*)d_in[6];
    const float* lr_w   = (const float*)d_in[7];
    const float* lr_b   = (const float*)d_in[8];
    const float* le_w   = (const float*)d_in[9];
    const float* att    = (const float*)d_in[10];
    const float* cb     = (const float*)d_in[11];
    const float* lng    = (const float*)d_in[12];
    const float* lnb    = (const float*)d_in[13];
    const float* hw1    = (const float*)d_in[14];
    const float* hb1    = (const float*)d_in[15];
    const float* hw2    = (const float*)d_in[16];
    const float* hb2    = (const float*)d_in[17];
    float* out = (float*)d_out;

    const int* src = ei;
    const int* dst = ei + EE;

    float *ph, *pxl, *pxr;
    cudaGetSymbolAddress((void**)&ph,  g_h);
    cudaGetSymbolAddress((void**)&pxl, g_xl);
    cudaGetSymbolAddress((void**)&pxr, g_xr);

    // CSR build (once per call; reused by all 3 layers)
    k_zero<<<(NN + 256) / 256, 256>>>();
    k_count<<<(EE + 255) / 256, 256>>>(dst);
    k_scan<<<1, 1024>>>();
    k_fill<<<(EE + 255) / 256, 256>>>(dst);

    // input projection (persistent)
    k_proj<<<592, 96>>>(x, proj_w, proj_b, ph);

    for (int l = 0; l < 3; l++) {
        k_lin2<<<592, 192>>>(ph, ll_w + l * HID * HID, ll_b + l * HID,
                             lr_w + l * HID * HID, lr_b + l * HID, pxl, pxr);
        k_edge<<<1184, 256>>>(src, dst, eattr, le_w + l * EDIM * HID, att + l * HID);
        k_aggr<<<(NN + 7) / 8, 256>>>(src, cb + l * HID, lng + l * HID, lnb + l * HID);
    }

    k_head<<<(NN + 127) / 128, 128>>>(hw1, hb1, hw2, hb2, out);
}

// round 3
// speedup vs baseline: 1.4156x; 1.2361x over previous
#include <cuda_runtime.h>
#include <math.h>

#define NN 50000
#define EE 800000
#define NDIM 32
#define EDIM 16
#define HID 96
#define NHEAD 4
#define CPH 24

// ---------------- scratch (device globals; no runtime allocation) ----------
__device__ float  g_h[NN * HID];
__device__ float  g_xl[NN * HID];
__device__ float  g_xr[NN * HID];
__device__ int    g_rowptr[NN + 1];
__device__ int    g_cursor[NN];
__device__ int    g_eid[EE];
__device__ int    g_src_p[EE];          // src node id, CSR-permuted
__device__ float  g_eattr_p[EE * EDIM]; // edge attrs, CSR-permuted (51 MB)

// ---------------- CSR build ------------------------------------------------
__global__ void k_zero() {
    int i = blockIdx.x * blockDim.x + threadIdx.x;
    if (i <= NN) g_rowptr[i] = 0;
}

__global__ void k_count(const int* __restrict__ dst) {
    int e = blockIdx.x * blockDim.x + threadIdx.x;
    if (e < EE) atomicAdd(&g_rowptr[dst[e] + 1], 1);
}

// single-block scan, warp-scan hierarchy, 49 elems/thread
__global__ void __launch_bounds__(1024) k_scan() {
    const int TOT = NN + 1;
    const int CH = (TOT + 1023) / 1024;  // 49
    int t = threadIdx.x;
    int b = t * CH;
    int vals[CH];
    int sum = 0;
#pragma unroll
    for (int j = 0; j < CH; j++) {
        int i = b + j;
        int v = (i < TOT) ? g_rowptr[i] : 0;
        vals[j] = v;
        sum += v;
    }
    int lane = t & 31, wid = t >> 5;
    int x = sum;
#pragma unroll
    for (int o = 1; o < 32; o <<= 1) {
        int y = __shfl_up_sync(0xffffffffu, x, o);
        if (lane >= o) x += y;
    }
    __shared__ int wsum[32];
    if (lane == 31) wsum[wid] = x;
    __syncthreads();
    if (wid == 0) {
        int w = wsum[lane];
#pragma unroll
        for (int o = 1; o < 32; o <<= 1) {
            int y = __shfl_up_sync(0xffffffffu, w, o);
            if (lane >= o) w += y;
        }
        wsum[lane] = w;
    }
    __syncthreads();
    int run = x - sum + (wid ? wsum[wid - 1] : 0);  // exclusive prefix of this thread
#pragma unroll
    for (int j = 0; j < CH; j++) {
        int i = b + j;
        if (i < TOT) {
            run += vals[j];
            g_rowptr[i] = run;
            if (i < NN) g_cursor[i] = run;
        }
    }
}

__global__ void k_fill(const int* __restrict__ src, const int* __restrict__ dst) {
    int e = blockIdx.x * blockDim.x + threadIdx.x;
    if (e < EE) {
        int p = atomicAdd(&g_cursor[dst[e]], 1);
        g_eid[p] = e;
        g_src_p[p] = src[e];
    }
}

// permute edge attrs into CSR order (sequential reads in the hot loop)
__global__ void k_perm(const float* __restrict__ eattr) {
    int i = blockIdx.x * blockDim.x + threadIdx.x;
    if (i < EE) {
        int e = g_eid[i];
        const float4* s = (const float4*)(eattr + e * EDIM);
        float4* d = (float4*)(g_eattr_p + (long)i * EDIM);
        d[0] = s[0]; d[1] = s[1]; d[2] = s[2]; d[3] = s[3];
    }
}

// ---------------- proj: out[N,96] = in[N,32] @ W + b (persistent) ----------
__global__ void __launch_bounds__(96) k_proj(const float* __restrict__ in,
                                             const float* __restrict__ W,
                                             const float* __restrict__ bias,
                                             float* __restrict__ out) {
    __shared__ float h_sh[16 * NDIM];
    int tid = threadIdx.x;
    float wreg[NDIM];
#pragma unroll
    for (int k = 0; k < NDIM; k++) wreg[k] = W[k * HID + tid];
    float bv = bias[tid];
    for (int n0 = blockIdx.x * 16; n0 < NN; n0 += gridDim.x * 16) {
        __syncthreads();
        for (int idx = tid; idx < 16 * NDIM; idx += 96) {
            int nn = n0 + idx / NDIM;
            h_sh[idx] = (nn < NN) ? in[n0 * NDIM + idx] : 0.f;
        }
        __syncthreads();
        float acc[16];
#pragma unroll
        for (int j = 0; j < 16; j++) acc[j] = bv;
#pragma unroll
        for (int k = 0; k < NDIM; k += 4) {
#pragma unroll
            for (int j = 0; j < 16; j++) {
                float4 hv = *(const float4*)&h_sh[j * NDIM + k];
                acc[j] = fmaf(hv.x, wreg[k + 0], acc[j]);
                acc[j] = fmaf(hv.y, wreg[k + 1], acc[j]);
                acc[j] = fmaf(hv.z, wreg[k + 2], acc[j]);
                acc[j] = fmaf(hv.w, wreg[k + 3], acc[j]);
            }
        }
#pragma unroll
        for (int j = 0; j < 16; j++)
            if (n0 + j < NN) out[(n0 + j) * HID + tid] = acc[j];
    }
}

// ---------------- fused lin_l + lin_r (persistent, weights in registers) ---
__global__ void __launch_bounds__(192) k_lin2(const float* __restrict__ in,
                                              const float* __restrict__ Wl,
                                              const float* __restrict__ bl,
                                              const float* __restrict__ Wr,
                                              const float* __restrict__ br,
                                              float* __restrict__ outl,
                                              float* __restrict__ outr) {
    __shared__ float h_sh[16 * HID];
    int tid = threadIdx.x;
    int col = tid % 96;
    bool isR = tid >= 96;
    const float* W = isR ? Wr : Wl;
    float wreg[HID];
#pragma unroll
    for (int k = 0; k < HID; k++) wreg[k] = W[k * HID + col];
    float bv = isR ? br[col] : bl[col];
    float* out = isR ? outr : outl;

    for (int n0 = blockIdx.x * 16; n0 < NN; n0 += gridDim.x * 16) {
        __syncthreads();
        for (int idx = tid; idx < 16 * HID; idx += 192) {
            int nn = n0 + idx / HID;
            h_sh[idx] = (nn < NN) ? in[n0 * HID + idx] : 0.f;
        }
        __syncthreads();
        float acc[16];
#pragma unroll
        for (int j = 0; j < 16; j++) acc[j] = bv;
#pragma unroll
        for (int k = 0; k < HID; k += 4) {
#pragma unroll
            for (int j = 0; j < 16; j++) {
                float4 hv = *(const float4*)&h_sh[j * HID + k];
                acc[j] = fmaf(hv.x, wreg[k + 0], acc[j]);
                acc[j] = fmaf(hv.y, wreg[k + 1], acc[j]);
                acc[j] = fmaf(hv.z, wreg[k + 2], acc[j]);
                acc[j] = fmaf(hv.w, wreg[k + 3], acc[j]);
            }
        }
#pragma unroll
        for (int j = 0; j < 16; j++)
            if (n0 + j < NN) out[(n0 + j) * HID + col] = acc[j];
    }
}

// ---------------- fused GATv2 layer: logits + online softmax + aggregate ---
// + residual + LayerNorm. Warp per node (persistent).
// Lane owns channels [3*lane, 3*lane+2]  ->  head = lane/8 (8 lanes/head).
__global__ void __launch_bounds__(256) k_layer(const float* __restrict__ We,
                                               const float* __restrict__ att,
                                               const float* __restrict__ cb,
                                               const float* __restrict__ lng,
                                               const float* __restrict__ lnb) {
    __shared__ float We_sh[EDIM * HID];
    __shared__ float att_sh[HID];
    int tid = threadIdx.x;
    for (int i = tid; i < EDIM * HID; i += 256) We_sh[i] = We[i];
    if (tid < HID) att_sh[tid] = att[tid];
    __syncthreads();

    int lane = tid & 31;
    int w = tid >> 5;
    int c = 3 * lane;
    float at0 = att_sh[c], at1 = att_sh[c + 1], at2 = att_sh[c + 2];

    for (int n = blockIdx.x * 8 + w; n < NN; n += gridDim.x * 8) {
        int r0 = g_rowptr[n], r1 = g_rowptr[n + 1];
        float xr0 = g_xr[n * HID + c];
        float xr1 = g_xr[n * HID + c + 1];
        float xr2 = g_xr[n * HID + c + 2];

        float mx = -3e38f, s = 0.f;
        float acc0 = 0.f, acc1 = 0.f, acc2 = 0.f;

        for (int i = r0; i < r1; i++) {
            int sidx = g_src_p[i];
            float ea = (lane < EDIM) ? g_eattr_p[(long)i * EDIM + lane] : 0.f;
            const float* xlp = g_xl + sidx * HID;
            float xl0 = xlp[c], xl1 = xlp[c + 1], xl2 = xlp[c + 2];

            float e0 = 0.f, e1 = 0.f, e2 = 0.f;
#pragma unroll
            for (int k = 0; k < EDIM; k++) {
                float a = __shfl_sync(0xffffffffu, ea, k);
                e0 = fmaf(a, We_sh[k * HID + c], e0);
                e1 = fmaf(a, We_sh[k * HID + c + 1], e1);
                e2 = fmaf(a, We_sh[k * HID + c + 2], e2);
            }
            float m0 = xl0 + xr0 + e0;
            float m1 = xl1 + xr1 + e1;
            float m2 = xl2 + xr2 + e2;
            m0 = fmaxf(m0, 0.2f * m0);
            m1 = fmaxf(m1, 0.2f * m1);
            m2 = fmaxf(m2, 0.2f * m2);
            float v = m0 * at0 + m1 * at1 + m2 * at2;
            // per-head reduce within 8-lane group
            v += __shfl_xor_sync(0xffffffffu, v, 4);
            v += __shfl_xor_sync(0xffffffffu, v, 2);
            v += __shfl_xor_sync(0xffffffffu, v, 1);
            // online softmax update (per lane; all lanes of a group identical)
            float nm = fmaxf(mx, v);
            float sc = __expf(mx - nm);
            float p  = __expf(v - nm);
            s = fmaf(s, sc, p);
            acc0 = fmaf(acc0, sc, p * xl0);
            acc1 = fmaf(acc1, sc, p * xl1);
            acc2 = fmaf(acc2, sc, p * xl2);
            mx = nm;
        }
        float inv = 1.f / (s + 1e-16f);
        float h0 = g_h[n * HID + c]     + acc0 * inv + cb[c];
        float h1 = g_h[n * HID + c + 1] + acc1 * inv + cb[c + 1];
        float h2 = g_h[n * HID + c + 2] + acc2 * inv + cb[c + 2];
        // LayerNorm over 96 channels (warp-wide)
        float sm = h0 + h1 + h2;
#pragma unroll
        for (int off = 16; off; off >>= 1) sm += __shfl_xor_sync(0xffffffffu, sm, off);
        float mu = sm * (1.f / 96.f);
        float d0 = h0 - mu, d1 = h1 - mu, d2 = h2 - mu;
        float vv = d0 * d0 + d1 * d1 + d2 * d2;
#pragma unroll
        for (int off = 16; off; off >>= 1) vv += __shfl_xor_sync(0xffffffffu, vv, off);
        float rs = rsqrtf(vv * (1.f / 96.f) + 1e-5f);
        g_h[n * HID + c]     = d0 * rs * lng[c]     + lnb[c];
        g_h[n * HID + c + 1] = d1 * rs * lng[c + 1] + lnb[c + 1];
        g_h[n * HID + c + 2] = d2 * rs * lng[c + 2] + lnb[c + 2];
    }
}

// ---------------- MLP head -------------------------------------------------
__global__ void __launch_bounds__(128) k_head(const float* __restrict__ w1,
                                              const float* __restrict__ b1,
                                              const float* __restrict__ w2,
                                              const float* __restrict__ b2,
                                              float* __restrict__ out) {
    __shared__ float w1s[HID * 48];
    __shared__ float b1s[48];
    __shared__ float w2s[48];
    int tid = threadIdx.x;
    for (int i = tid; i < HID * 48; i += 128) w1s[i] = w1[i];
    if (tid < 48) { b1s[tid] = b1[tid]; w2s[tid] = w2[tid]; }
    __syncthreads();
    int node = blockIdx.x * 128 + tid;
    if (node >= NN) return;

    float hreg[HID];
#pragma unroll
    for (int k = 0; k < HID; k += 4) {
        float4 v = *(const float4*)&g_h[node * HID + k];
        hreg[k] = v.x; hreg[k + 1] = v.y; hreg[k + 2] = v.z; hreg[k + 3] = v.w;
    }
    float y = 0.f;
#pragma unroll 2
    for (int j = 0; j < 48; j += 4) {
        float a0 = b1s[j], a1 = b1s[j + 1], a2 = b1s[j + 2], a3 = b1s[j + 3];
#pragma unroll
        for (int k = 0; k < HID; k++) {
            float4 wv = *(const float4*)&w1s[k * 48 + j];
            a0 = fmaf(hreg[k], wv.x, a0);
            a1 = fmaf(hreg[k], wv.y, a1);
            a2 = fmaf(hreg[k], wv.z, a2);
            a3 = fmaf(hreg[k], wv.w, a3);
        }
        float g0 = 0.5f * a0 * (1.f + erff(a0 * 0.70710678118654752f));
        float g1 = 0.5f * a1 * (1.f + erff(a1 * 0.70710678118654752f));
        float g2 = 0.5f * a2 * (1.f + erff(a2 * 0.70710678118654752f));
        float g3 = 0.5f * a3 * (1.f + erff(a3 * 0.70710678118654752f));
        y = fmaf(g0, w2s[j], y);
        y = fmaf(g1, w2s[j + 1], y);
        y = fmaf(g2, w2s[j + 2], y);
        y = fmaf(g3, w2s[j + 3], y);
    }
    out[node] = y + b2[0];
}

// ---------------- launch ---------------------------------------------------
extern "C" void kernel_launch(void* const* d_in, const int* in_sizes, int n_in,
                              void* d_out, int out_size) {
    const float* x      = (const float*)d_in[0];
    const int*   ei     = (const int*)d_in[1];
    const float* eattr  = (const float*)d_in[2];
    const float* proj_w = (const float*)d_in[3];
    const float* proj_b = (const float*)d_in[4];
    const float* ll_w   = (const float*)d_in[5];
    const float* ll_b   = (const float*)d_in[6];
    const float* lr_w   = (const float*)d_in[7];
    const float* lr_b   = (const float*)d_in[8];
    const float* le_w   = (const float*)d_in[9];
    const float* att    = (const float*)d_in[10];
    const float* cb     = (const float*)d_in[11];
    const float* lng    = (const float*)d_in[12];
    const float* lnb    = (const float*)d_in[13];
    const float* hw1    = (const float*)d_in[14];
    const float* hb1    = (const float*)d_in[15];
    const float* hw2    = (const float*)d_in[16];
    const float* hb2    = (const float*)d_in[17];
    float* out = (float*)d_out;

    const int* src = ei;
    const int* dst = ei + EE;

    float *ph, *pxl, *pxr;
    cudaGetSymbolAddress((void**)&ph,  g_h);
    cudaGetSymbolAddress((void**)&pxl, g_xl);
    cudaGetSymbolAddress((void**)&pxr, g_xr);

    // CSR build + edge permutation (once per call)
    k_zero<<<(NN + 256) / 256, 256>>>();
    k_count<<<(EE + 255) / 256, 256>>>(dst);
    k_scan<<<1, 1024>>>();
    k_fill<<<(EE + 255) / 256, 256>>>(src, dst);
    k_perm<<<(EE + 255) / 256, 256>>>(eattr);

    // input projection (persistent)
    k_proj<<<592, 96>>>(x, proj_w, proj_b, ph);

    for (int l = 0; l < 3; l++) {
        k_lin2<<<592, 192>>>(ph, ll_w + l * HID * HID, ll_b + l * HID,
                             lr_w + l * HID * HID, lr_b + l * HID, pxl, pxr);
        k_layer<<<592, 256>>>(le_w + l * EDIM * HID, att + l * HID,
                              cb + l * HID, lng + l * HID, lnb + l * HID);
    }

    k_head<<<(NN + 127) / 128, 128>>>(hw1, hb1, hw2, hb2, out);
}